// round 10
// baseline (speedup 1.0000x reference)
#include <cuda_runtime.h>
#include <cmath>

// Problem constants
#define NN_  8192
#define DD_  768
#define HH1_ 512
#define HH2_ 256

// ---------------- device scratch (static globals: allocation-guard legal) ----
__device__ float g_S [67108864];          // 8192*8192  (256 MiB) attention scores / P'
__device__ float g_Q [NN_ * DD_];
__device__ float g_K [NN_ * DD_];
__device__ float g_V [NN_ * DD_];         // X @ Wg (tf32-rounded)
__device__ float g_Y [NN_ * DD_];         // X + M  (tf32-rounded)
__device__ float g_H1[NN_ * HH1_];
__device__ float g_H2[NN_ * HH2_];
__device__ float g_G [NN_];
__device__ float g_rowM[NN_];
__device__ float g_rowS[NN_];
// tf32-rounded copies of inputs used as GEMM operands
__device__ float g_Xtf [NN_ * DD_];
__device__ float g_Wqt [DD_ * DD_];
__device__ float g_Wkt [DD_ * DD_];
__device__ float g_Wgt [DD_ * DD_];
__device__ float g_W1a [DD_ * HH1_];
__device__ float g_W2a [HH1_ * HH2_];
__device__ float g_W1b [DD_ * HH1_];
__device__ float g_W2b [HH1_ * HH2_];

// ---------------- math helpers ---------------------------------------------
__device__ __forceinline__ float gelu_exact(float x) {
    return 0.5f * x * (1.0f + erff(x * 0.70710678118654752440f));
}
__device__ __forceinline__ float softplus_(float x) {
    return fmaxf(x, 0.0f) + log1pf(expf(-fabsf(x)));
}
__device__ __forceinline__ unsigned f2tf(float f) {
    unsigned r;
    asm("cvt.rna.tf32.f32 %0, %1;" : "=r"(r) : "f"(f));
    return r;
}
__device__ __forceinline__ float tfround(float f) {
    return __uint_as_float(f2tf(f));
}
__device__ __forceinline__ void mma_tf32(float* c, const unsigned* a, const unsigned* b) {
    asm volatile(
        "mma.sync.aligned.m16n8k8.row.col.f32.tf32.tf32.f32 "
        "{%0,%1,%2,%3}, {%4,%5,%6,%7}, {%8,%9}, {%0,%1,%2,%3};"
        : "+f"(c[0]), "+f"(c[1]), "+f"(c[2]), "+f"(c[3])
        : "r"(a[0]), "r"(a[1]), "r"(a[2]), "r"(a[3]), "r"(b[0]), "r"(b[1]));
}

// ---------------- elementwise tf32 rounding (prep pass) ----------------------
__global__ void cvt_tf32_kernel(const float* __restrict__ in, float* __restrict__ outp) {
    const int i = (blockIdx.x * 256 + threadIdx.x) * 4;
    float4 v = *(const float4*)(in + i);
    v.x = tfround(v.x); v.y = tfround(v.y); v.z = tfround(v.z); v.w = tfround(v.w);
    *(float4*)(outp + i) = v;
}

// ---------------- 128x128x16 double-buffered TF32 tensor-core GEMM ----------
// All A/B operands must already be tf32-rounded floats (no in-loop cvt).
// C[M,Nn] = epi( scale * A[M,K] @ op(B) )
//   TRANSB=false: B is [K,Nn] row-major;  TRANSB=true: B is [Nn,K] row-major (C=A*B^T)
//   EPI 0: C = acc*scale
//   EPI 1: C = gelu(acc + bias[col])
//   EPI 2: C = addsrc[row,col] + gelu(acc + bias[col])
//   CVT  : round C to tf32 before store (when C feeds another GEMM)
// Requires: M%128==0, Nn%128==0, K%16==0.
//
// Smem layout for A (and B when TRANSB): per-row 16 k-words stored pair-
// permuted: word(k) = (k/8)*8 + (k%4)*2 + ((k%8)/4). This makes the
// (c0, c0+4) pair a thread needs for one MMA contiguous -> LDS.64.
// Row pitch 24 words: fragment LDS.64 covers banks 0..31 exactly (conflict-free).
template<bool TRANSB, int EPI, bool CVT>
__global__ __launch_bounds__(256)
void tgemm(const float* __restrict__ A, const float* __restrict__ B,
           float* __restrict__ C, int M, int Nn, int K,
           const float* __restrict__ bias, const float* __restrict__ addsrc,
           float scale)
{
    constexpr int KT = 16;
    __shared__ unsigned As[2][128][24];
    constexpr int BR = TRANSB ? 128 : 16;
    constexpr int BS = TRANSB ? 24  : 136;
    __shared__ unsigned Bs[2][BR][BS];

    const int tid  = threadIdx.x;
    const int lane = tid & 31;
    const int warp = tid >> 5;
    const int warpM = (warp & 1) * 64;   // 2 warps along M
    const int warpN = (warp >> 1) * 32;  // 4 warps along N
    const int rowBase = blockIdx.y * 128, colBase = blockIdx.x * 128;

    // A loader: rows ldRow and ldRow+64, k = ldK..ldK+3 (float4)
    const int ldRow = tid >> 2;            // 0..63
    const int ldK   = (tid & 3) * 4;       // 0,4,8,12
    const int w0    = (ldK & 8) | ((ldK >> 2) & 1);   // permuted base word
    const float* gA = A + (size_t)(rowBase + ldRow) * K + ldK;

    // B loader
    const float* gB;
    int bK = 0, bN = 0;
    if (TRANSB) {
        gB = B + (size_t)(colBase + ldRow) * K + ldK;
    } else {
        bK = tid >> 5;            // 0..7, second at +8
        bN = (tid & 31) * 4;      // 0..124
        gB = B + (size_t)bK * Nn + colBase + bN;
    }

    float acc[4][4][4];
#pragma unroll
    for (int i = 0; i < 4; i++)
#pragma unroll
        for (int j = 0; j < 4; j++)
#pragma unroll
            for (int q = 0; q < 4; q++) acc[i][j][q] = 0.0f;

    float4 ra0, ra1, rb0, rb1;

    auto stPermA = [&](int buf, int row, float4 v) {
        As[buf][row][w0 + 0] = __float_as_uint(v.x);
        As[buf][row][w0 + 2] = __float_as_uint(v.y);
        As[buf][row][w0 + 4] = __float_as_uint(v.z);
        As[buf][row][w0 + 6] = __float_as_uint(v.w);
    };

    // prologue: load tile 0
    ra0 = *(const float4*)(gA);
    ra1 = *(const float4*)(gA + (size_t)64 * K);
    if (TRANSB) {
        rb0 = *(const float4*)(gB);
        rb1 = *(const float4*)(gB + (size_t)64 * K);
    } else {
        rb0 = *(const float4*)(gB);
        rb1 = *(const float4*)(gB + (size_t)8 * Nn);
    }
    stPermA(0, ldRow, ra0);
    stPermA(0, ldRow + 64, ra1);
    if (TRANSB) {
        Bs[0][ldRow][w0 + 0] = __float_as_uint(rb0.x);
        Bs[0][ldRow][w0 + 2] = __float_as_uint(rb0.y);
        Bs[0][ldRow][w0 + 4] = __float_as_uint(rb0.z);
        Bs[0][ldRow][w0 + 6] = __float_as_uint(rb0.w);
        Bs[0][ldRow + 64][w0 + 0] = __float_as_uint(rb1.x);
        Bs[0][ldRow + 64][w0 + 2] = __float_as_uint(rb1.y);
        Bs[0][ldRow + 64][w0 + 4] = __float_as_uint(rb1.z);
        Bs[0][ldRow + 64][w0 + 6] = __float_as_uint(rb1.w);
    } else {
        *(uint4*)&Bs[0][bK][bN]     = *(const uint4*)&rb0;
        *(uint4*)&Bs[0][bK + 8][bN] = *(const uint4*)&rb1;
    }
    __syncthreads();

    const int r0 = lane >> 2;      // 0..7
    const int c0 = lane & 3;       // 0..3
    const int ntiles = K / KT;

    for (int t = 0; t < ntiles; t++) {
        const int cur = t & 1, nxt = cur ^ 1;
        const bool more = (t + 1 < ntiles);
        if (more) {
            ra0 = *(const float4*)(gA + (t + 1) * KT);
            ra1 = *(const float4*)(gA + (t + 1) * KT + (size_t)64 * K);
            if (TRANSB) {
                rb0 = *(const float4*)(gB + (t + 1) * KT);
                rb1 = *(const float4*)(gB + (t + 1) * KT + (size_t)64 * K);
            } else {
                rb0 = *(const float4*)(gB + (size_t)(t + 1) * KT * Nn);
                rb1 = *(const float4*)(gB + (size_t)((t + 1) * KT + 8) * Nn);
            }
        }
        // compute on cur buffer: 2 k-steps of 8
#pragma unroll
        for (int ks = 0; ks < 2; ks++) {
            const int kb = ks * 8 + 2 * c0;   // 64-bit pair word (even -> aligned)
            unsigned af[4][4];
#pragma unroll
            for (int i = 0; i < 4; i++) {
                const int m0 = warpM + i * 16;
                uint2 alo = *(const uint2*)&As[cur][m0 + r0    ][kb];
                uint2 ahi = *(const uint2*)&As[cur][m0 + r0 + 8][kb];
                af[i][0] = alo.x; af[i][1] = ahi.x; af[i][2] = alo.y; af[i][3] = ahi.y;
            }
            unsigned bf[4][2];
#pragma unroll
            for (int j = 0; j < 4; j++) {
                const int n0 = warpN + j * 8;
                if (TRANSB) {
                    uint2 bv = *(const uint2*)&Bs[cur][n0 + r0][kb];
                    bf[j][0] = bv.x; bf[j][1] = bv.y;
                } else {
                    bf[j][0] = Bs[cur][ks * 8 + c0    ][n0 + r0];
                    bf[j][1] = Bs[cur][ks * 8 + c0 + 4][n0 + r0];
                }
            }
#pragma unroll
            for (int i = 0; i < 4; i++)
#pragma unroll
                for (int j = 0; j < 4; j++)
                    mma_tf32(acc[i][j], af[i], bf[j]);
        }
        if (more) {
            stPermA(nxt, ldRow, ra0);
            stPermA(nxt, ldRow + 64, ra1);
            if (TRANSB) {
                Bs[nxt][ldRow][w0 + 0] = __float_as_uint(rb0.x);
                Bs[nxt][ldRow][w0 + 2] = __float_as_uint(rb0.y);
                Bs[nxt][ldRow][w0 + 4] = __float_as_uint(rb0.z);
                Bs[nxt][ldRow][w0 + 6] = __float_as_uint(rb0.w);
                Bs[nxt][ldRow + 64][w0 + 0] = __float_as_uint(rb1.x);
                Bs[nxt][ldRow + 64][w0 + 2] = __float_as_uint(rb1.y);
                Bs[nxt][ldRow + 64][w0 + 4] = __float_as_uint(rb1.z);
                Bs[nxt][ldRow + 64][w0 + 6] = __float_as_uint(rb1.w);
            } else {
                *(uint4*)&Bs[nxt][bK][bN]     = *(const uint4*)&rb0;
                *(uint4*)&Bs[nxt][bK + 8][bN] = *(const uint4*)&rb1;
            }
        }
        __syncthreads();
    }

    // epilogue: fragment m16n8 -> c0,c1 at (r0, 2c), c2,c3 at (r0+8, 2c)
    const int cc = (lane & 3) * 2;
#pragma unroll
    for (int i = 0; i < 4; i++) {
        const int gr = rowBase + warpM + i * 16 + r0;
#pragma unroll
        for (int j = 0; j < 4; j++) {
            const int gc = colBase + warpN + j * 8 + cc;
#pragma unroll
            for (int half = 0; half < 2; half++) {
                const int row = gr + half * 8;
                float v0 = acc[i][j][half * 2 + 0] * scale;
                float v1 = acc[i][j][half * 2 + 1] * scale;
                if (EPI == 1) {
                    v0 = gelu_exact(v0 + bias[gc]);
                    v1 = gelu_exact(v1 + bias[gc + 1]);
                } else if (EPI == 2) {
                    const float* ap = addsrc + (size_t)row * Nn + gc;
                    v0 = ap[0] + gelu_exact(v0 + bias[gc]);
                    v1 = ap[1] + gelu_exact(v1 + bias[gc + 1]);
                }
                if (CVT) { v0 = tfround(v0); v1 = tfround(v1); }
                *(float2*)(C + (size_t)row * Nn + gc) = make_float2(v0, v1);
            }
        }
    }
}

// ---------------- NIG head final: r = H2 @ Wh + bh, then nonlinearities ------
__global__ void head_final(const float* __restrict__ H2, const float* __restrict__ Wh,
                           const float* __restrict__ bh, float* __restrict__ out,
                           int outOff, float* __restrict__ Gbuf,
                           const float* __restrict__ gamp, int N)
{
    const int warp = threadIdx.x >> 5, lane = threadIdx.x & 31;
    const int row = blockIdx.x * 8 + warp;

    float4 acc = make_float4(0.f, 0.f, 0.f, 0.f);
    const float* h = H2 + (size_t)row * HH2_ + lane * 8;
#pragma unroll
    for (int i = 0; i < 8; i++) {
        float hv = h[i];
        float4 w = *(const float4*)&Wh[(lane * 8 + i) * 4];
        acc.x = fmaf(hv, w.x, acc.x);
        acc.y = fmaf(hv, w.y, acc.y);
        acc.z = fmaf(hv, w.z, acc.z);
        acc.w = fmaf(hv, w.w, acc.w);
    }
#pragma unroll
    for (int off = 16; off > 0; off >>= 1) {
        acc.x += __shfl_xor_sync(0xffffffffu, acc.x, off);
        acc.y += __shfl_xor_sync(0xffffffffu, acc.y, off);
        acc.z += __shfl_xor_sync(0xffffffffu, acc.z, off);
        acc.w += __shfl_xor_sync(0xffffffffu, acc.w, off);
    }
    if (lane == 0) {
        float mu = acc.x + bh[0];
        float v  = softplus_(acc.y + bh[1]) + 1e-6f;
        float a  = softplus_(acc.z + bh[2]) + 1.0f + 1e-6f;
        float b  = softplus_(acc.w + bh[3]) + 1e-6f;
        out[outOff + 0 * N + row] = mu;
        out[outOff + 1 * N + row] = v;
        out[outOff + 2 * N + row] = a;
        out[outOff + 3 * N + row] = b;
        if (Gbuf) {
            float u0  = b / fmaxf(a - 1.0f, 1e-8f);
            float sig = 1.0f / (1.0f + expf(-u0));
            Gbuf[row] = 1.0f - gamp[0] * sig;
        }
    }
}

// ---------------- per-row softmax stats with G weighting ---------------------
__global__ void softmax_stats(const float* __restrict__ S, const float* __restrict__ G,
                              float* __restrict__ rowM, float* __restrict__ rowSc, int N)
{
    const int row = blockIdx.x;
    const float* s = S + (size_t)row * N;
    float m = -INFINITY, Z = 0.f, W = 0.f;
    for (int j = threadIdx.x * 4; j < N; j += 1024) {
        float4 x = *(const float4*)(s + j);
        float4 g = *(const float4*)(G + j);
        float xv[4] = {x.x, x.y, x.z, x.w};
        float gv[4] = {g.x, g.y, g.z, g.w};
#pragma unroll
        for (int q = 0; q < 4; q++) {
            float xx = xv[q];
            if (xx > m) {
                float e = expf(m - xx);
                Z *= e; W *= e; m = xx;
            }
            float p = expf(xx - m);
            Z += p; W = fmaf(p, gv[q], W);
        }
    }
    __shared__ float sm[256], sZ[256], sW[256];
    sm[threadIdx.x] = m; sZ[threadIdx.x] = Z; sW[threadIdx.x] = W;
    __syncthreads();
    for (int off = 128; off > 0; off >>= 1) {
        if (threadIdx.x < off) {
            float m1 = sm[threadIdx.x],       Z1 = sZ[threadIdx.x],       W1 = sW[threadIdx.x];
            float m2 = sm[threadIdx.x + off], Z2 = sZ[threadIdx.x + off], W2 = sW[threadIdx.x + off];
            float mn = fmaxf(m1, m2);
            float e1 = expf(m1 - mn), e2 = expf(m2 - mn);
            sm[threadIdx.x] = mn;
            sZ[threadIdx.x] = Z1 * e1 + Z2 * e2;
            sW[threadIdx.x] = W1 * e1 + W2 * e2;
        }
        __syncthreads();
    }
    if (threadIdx.x == 0) {
        float mF = sm[0], ZF = sZ[0], WF = sW[0];
        float Gi = G[row];
        float rowsum = Gi * WF / ZF;
        float sc = (Gi / ZF) / fmaxf(rowsum, 1e-8f);
        rowM[row] = mF; rowSc[row] = sc;
    }
}

// ---------------- in-place rescale: S <- tf32(exp(S-m)*G_j*s_i) --------------
__global__ void rescale_kernel(float* __restrict__ S, const float* __restrict__ G,
                               const float* __restrict__ rowM, const float* __restrict__ rowSc,
                               int N)
{
    const int row = blockIdx.y;
    const int j = blockIdx.x * 1024 + threadIdx.x * 4;
    const float m = rowM[row], sc = rowSc[row];
    float4* p = (float4*)(S + (size_t)row * N + j);
    float4 v = *p;
    const float4 g = *(const float4*)(G + j);
    v.x = tfround(expf(v.x - m) * g.x * sc);
    v.y = tfround(expf(v.y - m) * g.y * sc);
    v.z = tfround(expf(v.z - m) * g.z * sc);
    v.w = tfround(expf(v.w - m) * g.w * sc);
    *p = v;
}

// ---------------- launcher ---------------------------------------------------
extern "C" void kernel_launch(void* const* d_in, const int* in_sizes, int n_in,
                              void* d_out, int out_size)
{
    (void)in_sizes; (void)n_in; (void)out_size;

    const float* X    = (const float*)d_in[0];
    const float* Wq   = (const float*)d_in[1];
    const float* Wk   = (const float*)d_in[2];
    const float* Wg   = (const float*)d_in[3];
    const float* bg   = (const float*)d_in[4];
    const float* gam  = (const float*)d_in[5];
    const float* ihW1 = (const float*)d_in[6];
    const float* ihb1 = (const float*)d_in[7];
    const float* ihW2 = (const float*)d_in[8];
    const float* ihb2 = (const float*)d_in[9];
    const float* ihWh = (const float*)d_in[10];
    const float* ihbh = (const float*)d_in[11];
    const float* fhW1 = (const float*)d_in[12];
    const float* fhb1 = (const float*)d_in[13];
    const float* fhW2 = (const float*)d_in[14];
    const float* fhb2 = (const float*)d_in[15];
    const float* fhWh = (const float*)d_in[16];
    const float* fhbh = (const float*)d_in[17];
    float* out = (float*)d_out;

    float *S, *Q, *Kp, *V, *Y, *H1b, *H2b, *G, *rM, *rS;
    float *Xtf, *Wqt, *Wkt, *Wgt, *W1a, *W2a, *W1b, *W2b;
    cudaGetSymbolAddress((void**)&S,   g_S);
    cudaGetSymbolAddress((void**)&Q,   g_Q);
    cudaGetSymbolAddress((void**)&Kp,  g_K);
    cudaGetSymbolAddress((void**)&V,   g_V);
    cudaGetSymbolAddress((void**)&Y,   g_Y);
    cudaGetSymbolAddress((void**)&H1b, g_H1);
    cudaGetSymbolAddress((void**)&H2b, g_H2);
    cudaGetSymbolAddress((void**)&G,   g_G);
    cudaGetSymbolAddress((void**)&rM,  g_rowM);
    cudaGetSymbolAddress((void**)&rS,  g_rowS);
    cudaGetSymbolAddress((void**)&Xtf, g_Xtf);
    cudaGetSymbolAddress((void**)&Wqt, g_Wqt);
    cudaGetSymbolAddress((void**)&Wkt, g_Wkt);
    cudaGetSymbolAddress((void**)&Wgt, g_Wgt);
    cudaGetSymbolAddress((void**)&W1a, g_W1a);
    cudaGetSymbolAddress((void**)&W2a, g_W2a);
    cudaGetSymbolAddress((void**)&W1b, g_W1b);
    cudaGetSymbolAddress((void**)&W2b, g_W2b);

    const int N = NN_, D = DD_, H1 = HH1_, H2 = HH2_;
    const float invSqrtD = 1.0f / sqrtf((float)D);

    // ---- tf32 rounding of inputs used as GEMM operands ----
    cvt_tf32_kernel<<<(N * D) / 1024, 256>>>(X, Xtf);
    cvt_tf32_kernel<<<(D * D) / 1024, 256>>>(Wq, Wqt);
    cvt_tf32_kernel<<<(D * D) / 1024, 256>>>(Wk, Wkt);
    cvt_tf32_kernel<<<(D * D) / 1024, 256>>>(Wg, Wgt);
    cvt_tf32_kernel<<<(D * H1) / 1024, 256>>>(ihW1, W1a);
    cvt_tf32_kernel<<<(H1 * H2) / 1024, 256>>>(ihW2, W2a);
    cvt_tf32_kernel<<<(D * H1) / 1024, 256>>>(fhW1, W1b);
    cvt_tf32_kernel<<<(H1 * H2) / 1024, 256>>>(fhW2, W2b);

    // ---- head 1 on X -> m0,v0,a0,b0 (out[0..4N)) and gate G ----
    tgemm<false, 1, true ><<<dim3(H1 / 128, N / 128), 256>>>(Xtf, W1a, H1b, N, H1, D,  ihb1, nullptr, 1.0f);
    tgemm<false, 1, false><<<dim3(H2 / 128, N / 128), 256>>>(H1b, W2a, H2b, N, H2, H1, ihb2, nullptr, 1.0f);
    head_final<<<N / 8, 256>>>(H2b, ihWh, ihbh, out, 0, G, gam, N);

    // ---- projections (outputs tf32-rounded: feed the S / PV GEMMs) ----
    tgemm<false, 0, true><<<dim3(D / 128, N / 128), 256>>>(Xtf, Wqt, Q,  N, D, D, nullptr, nullptr, 1.0f);
    tgemm<false, 0, true><<<dim3(D / 128, N / 128), 256>>>(Xtf, Wkt, Kp, N, D, D, nullptr, nullptr, 1.0f);
    tgemm<false, 0, true><<<dim3(D / 128, N / 128), 256>>>(Xtf, Wgt, V,  N, D, D, nullptr, nullptr, 1.0f);

    // ---- S = Q K^T / sqrt(D) (raw fp32 for softmax) ----
    tgemm<true, 0, false><<<dim3(N / 128, N / 128), 256>>>(Q, Kp, S, N, N, D, nullptr, nullptr, invSqrtD);

    // ---- softmax stats + gated row normalization folded into S (tf32 out) ----
    softmax_stats<<<N, 256>>>(S, G, rM, rS, N);
    rescale_kernel<<<dim3(N / 1024, N), 256>>>(S, G, rM, rS, N);

    // ---- Y = tf32(X + gelu(P' @ V + bg)) ----
    tgemm<false, 2, true><<<dim3(D / 128, N / 128), 256>>>(S, V, Y, N, D, N, bg, X, 1.0f);

    // ---- head 2 on Y -> mu,v,al,be (out[4N..8N)) ----
    tgemm<false, 1, true ><<<dim3(H1 / 128, N / 128), 256>>>(Y,   W1b, H1b, N, H1, D,  fhb1, nullptr, 1.0f);
    tgemm<false, 1, false><<<dim3(H2 / 128, N / 128), 256>>>(H1b, W2b, H2b, N, H2, H1, fhb2, nullptr, 1.0f);
    head_final<<<N / 8, 256>>>(H2b, fhWh, fhbh, out, 4 * N, nullptr, gam, N);
}

// round 12
// speedup vs baseline: 1.3094x; 1.3094x over previous
#include <cuda_runtime.h>
#include <cstdint>
#include <cmath>

// Problem constants
#define NN_  8192
#define DD_  768
#define HH1_ 512
#define HH2_ 256

// ---------------- device scratch (static globals: allocation-guard legal) ----
__device__ float g_S [67108864];          // 8192*8192 attention scores / P'
__device__ float g_Q [NN_ * DD_];
__device__ float g_K [NN_ * DD_];
__device__ float g_V [NN_ * DD_];         // X @ Wg (tf32-rounded)
__device__ float g_Y [NN_ * DD_];         // X + M  (tf32-rounded)
__device__ float g_H1[NN_ * HH1_];
__device__ float g_H2[NN_ * HH2_];
__device__ float g_G [NN_];
__device__ float g_Xtf [NN_ * DD_];
__device__ float g_Wqt [DD_ * DD_];
__device__ float g_Wkt [DD_ * DD_];
__device__ float g_Wgt [DD_ * DD_];
__device__ float g_W1a [DD_ * HH1_];
__device__ float g_W2a [HH1_ * HH2_];
__device__ float g_W1b [DD_ * HH1_];
__device__ float g_W2b [HH1_ * HH2_];

// ---------------- math helpers ---------------------------------------------
__device__ __forceinline__ float gelu_exact(float x) {
    return 0.5f * x * (1.0f + erff(x * 0.70710678118654752440f));
}
__device__ __forceinline__ float softplus_(float x) {
    return fmaxf(x, 0.0f) + log1pf(expf(-fabsf(x)));
}
__device__ __forceinline__ unsigned f2tf(float f) {
    unsigned r;
    asm("cvt.rna.tf32.f32 %0, %1;" : "=r"(r) : "f"(f));
    return r;
}
__device__ __forceinline__ float tfround(float f) {
    return __uint_as_float(f2tf(f));
}
__device__ __forceinline__ void mma_tf32(float* c, const unsigned* a, const unsigned* b) {
    asm volatile(
        "mma.sync.aligned.m16n8k8.row.col.f32.tf32.tf32.f32 "
        "{%0,%1,%2,%3}, {%4,%5,%6,%7}, {%8,%9}, {%0,%1,%2,%3};"
        : "+f"(c[0]), "+f"(c[1]), "+f"(c[2]), "+f"(c[3])
        : "r"(a[0]), "r"(a[1]), "r"(a[2]), "r"(a[3]), "r"(b[0]), "r"(b[1]));
}
__device__ __forceinline__ void cp_async16(unsigned dst, const float* src) {
    unsigned long long gsrc = __cvta_generic_to_global(src);
    asm volatile("cp.async.cg.shared.global [%0], [%1], 16;" :: "r"(dst), "l"(gsrc) : "memory");
}
__device__ __forceinline__ unsigned smem_addr(const void* p) {
    return (unsigned)__cvta_generic_to_shared(p);
}

// ---------------- elementwise tf32 rounding (prep pass) ----------------------
__global__ void cvt_tf32_kernel(const float* __restrict__ in, float* __restrict__ outp) {
    const int i = (blockIdx.x * 256 + threadIdx.x) * 4;
    float4 v = *(const float4*)(in + i);
    v.x = tfround(v.x); v.y = tfround(v.y); v.z = tfround(v.z); v.w = tfround(v.w);
    *(float4*)(outp + i) = v;
}

// ============================================================================
// 128x128x16 TF32 tensor-core GEMM with 4-stage cp.async pipeline.
// All A/B operands must already be tf32-rounded fp32 in gmem (HW truncation
// inside mma.sync is then exact).
// C[M,Nn] = epi( scale * A[M,K] @ op(B) )
//   TRANSB=false: B is [K,Nn] row-major;  TRANSB=true: B is [Nn,K] row-major
//   EPI 0: C = acc*scale
//   EPI 1: C = gelu(acc + bias[col])
//   EPI 2: C = addsrc[row,col] + gelu(acc + bias[col])
//   CVT  : round C to tf32 before store (when C feeds another GEMM)
// Requires: M%128==0, Nn%128==0, K%16==0, K/16 >= 3.
// ============================================================================
template<bool TRANSB, int EPI, bool CVT>
__global__ __launch_bounds__(256)
void tgemm(const float* __restrict__ A, const float* __restrict__ B,
           float* __restrict__ C, int M, int Nn, int K,
           const float* __restrict__ bias, const float* __restrict__ addsrc,
           float scale)
{
    constexpr int KT = 16, NSTAGE = 4;
    constexpr int AW = 128 * 20;                       // words per A stage
    constexpr int BW = TRANSB ? 128 * 20 : 16 * 136;   // words per B stage
    extern __shared__ unsigned sm[];
    unsigned* AsBase = sm;                    // [NSTAGE][128][20]
    unsigned* BsBase = sm + NSTAGE * AW;      // [NSTAGE][...]

    const int tid  = threadIdx.x;
    const int lane = tid & 31;
    const int warp = tid >> 5;
    const int warpM = (warp & 1) * 64;
    const int warpN = (warp >> 1) * 32;
    const int rowBase = blockIdx.y * 128, colBase = blockIdx.x * 128;

    // A loader: rows ldRow, ldRow+64; k = ldK..ldK+3 (one 16B cp.async each)
    const int ldRow = tid >> 2;            // 0..63
    const int ldK   = (tid & 3) * 4;       // 0,4,8,12
    const float* gA = A + (size_t)(rowBase + ldRow) * K + ldK;

    // B loader
    const float* gB;
    int bK = 0, bN = 0;
    if (TRANSB) {
        gB = B + (size_t)(colBase + ldRow) * K + ldK;
    } else {
        bK = tid >> 5;            // 0..7, second at +8
        bN = (tid & 31) * 4;      // 0..124
        gB = B + (size_t)bK * Nn + colBase + bN;
    }

    const unsigned aOff0 = ldRow * 20 + ldK;
    const unsigned aOff1 = (ldRow + 64) * 20 + ldK;

    auto load_tile = [&](int t, int s) {
        const unsigned aBase = smem_addr(AsBase + s * AW);
        cp_async16(aBase + aOff0 * 4, gA + t * KT);
        cp_async16(aBase + aOff1 * 4, gA + t * KT + (size_t)64 * K);
        const unsigned bBase = smem_addr(BsBase + s * BW);
        if (TRANSB) {
            cp_async16(bBase + aOff0 * 4, gB + t * KT);
            cp_async16(bBase + aOff1 * 4, gB + t * KT + (size_t)64 * K);
        } else {
            cp_async16(bBase + (bK * 136 + bN) * 4, gB + (size_t)t * KT * Nn);
            cp_async16(bBase + ((bK + 8) * 136 + bN) * 4, gB + (size_t)(t * KT + 8) * Nn);
        }
    };

    float acc[4][4][4];
#pragma unroll
    for (int i = 0; i < 4; i++)
#pragma unroll
        for (int j = 0; j < 4; j++)
#pragma unroll
            for (int q = 0; q < 4; q++) acc[i][j][q] = 0.0f;

    const int ntiles = K / KT;

    // prologue: stages 0..2 in flight, one commit group each
#pragma unroll
    for (int s = 0; s < NSTAGE - 1; s++) {
        load_tile(s, s);
        asm volatile("cp.async.commit_group;" ::: "memory");
    }

    const int r0 = lane >> 2;      // 0..7
    const int c0 = lane & 3;       // 0..3

    for (int t = 0; t < ntiles; t++) {
        asm volatile("cp.async.wait_group 2;" ::: "memory");
        __syncthreads();

        const int st = t & (NSTAGE - 1);
        const unsigned* As = AsBase + st * AW;
        const unsigned* Bs = BsBase + st * BW;

#pragma unroll
        for (int ks = 0; ks < 2; ks++) {
            const int k0 = ks * 8;
            unsigned af[4][4];
#pragma unroll
            for (int i = 0; i < 4; i++) {
                const int m0 = warpM + i * 16;
                af[i][0] = As[(m0 + r0)     * 20 + k0 + c0    ];
                af[i][1] = As[(m0 + r0 + 8) * 20 + k0 + c0    ];
                af[i][2] = As[(m0 + r0)     * 20 + k0 + c0 + 4];
                af[i][3] = As[(m0 + r0 + 8) * 20 + k0 + c0 + 4];
            }
            unsigned bf[4][2];
#pragma unroll
            for (int j = 0; j < 4; j++) {
                const int n0 = warpN + j * 8;
                if (TRANSB) {
                    bf[j][0] = Bs[(n0 + r0) * 20 + k0 + c0    ];
                    bf[j][1] = Bs[(n0 + r0) * 20 + k0 + c0 + 4];
                } else {
                    bf[j][0] = Bs[(k0 + c0)     * 136 + n0 + r0];
                    bf[j][1] = Bs[(k0 + c0 + 4) * 136 + n0 + r0];
                }
            }
#pragma unroll
            for (int i = 0; i < 4; i++)
#pragma unroll
                for (int j = 0; j < 4; j++)
                    mma_tf32(acc[i][j], af[i], bf[j]);
        }

        // issue next load into the stage freed by iteration t-1
        const int tn = t + NSTAGE - 1;
        if (tn < ntiles) load_tile(tn, tn & (NSTAGE - 1));
        asm volatile("cp.async.commit_group;" ::: "memory");
    }

    // epilogue: fragment m16n8 -> c0,c1 at (r0, 2c), c2,c3 at (r0+8, 2c)
    const int cc = (lane & 3) * 2;
#pragma unroll
    for (int i = 0; i < 4; i++) {
        const int gr = rowBase + warpM + i * 16 + r0;
#pragma unroll
        for (int j = 0; j < 4; j++) {
            const int gc = colBase + warpN + j * 8 + cc;
#pragma unroll
            for (int half = 0; half < 2; half++) {
                const int row = gr + half * 8;
                float v0 = acc[i][j][half * 2 + 0] * scale;
                float v1 = acc[i][j][half * 2 + 1] * scale;
                if (EPI == 1) {
                    v0 = gelu_exact(v0 + bias[gc]);
                    v1 = gelu_exact(v1 + bias[gc + 1]);
                } else if (EPI == 2) {
                    const float* ap = addsrc + (size_t)row * Nn + gc;
                    v0 = ap[0] + gelu_exact(v0 + bias[gc]);
                    v1 = ap[1] + gelu_exact(v1 + bias[gc + 1]);
                }
                if (CVT) { v0 = tfround(v0); v1 = tfround(v1); }
                *(float2*)(C + (size_t)row * Nn + gc) = make_float2(v0, v1);
            }
        }
    }
}

// ---------------- NIG head final ---------------------------------------------
__global__ void head_final(const float* __restrict__ H2, const float* __restrict__ Wh,
                           const float* __restrict__ bh, float* __restrict__ out,
                           int outOff, float* __restrict__ Gbuf,
                           const float* __restrict__ gamp, int N)
{
    const int warp = threadIdx.x >> 5, lane = threadIdx.x & 31;
    const int row = blockIdx.x * 8 + warp;

    float4 acc = make_float4(0.f, 0.f, 0.f, 0.f);
    const float* h = H2 + (size_t)row * HH2_ + lane * 8;
#pragma unroll
    for (int i = 0; i < 8; i++) {
        float hv = h[i];
        float4 w = *(const float4*)&Wh[(lane * 8 + i) * 4];
        acc.x = fmaf(hv, w.x, acc.x);
        acc.y = fmaf(hv, w.y, acc.y);
        acc.z = fmaf(hv, w.z, acc.z);
        acc.w = fmaf(hv, w.w, acc.w);
    }
#pragma unroll
    for (int off = 16; off > 0; off >>= 1) {
        acc.x += __shfl_xor_sync(0xffffffffu, acc.x, off);
        acc.y += __shfl_xor_sync(0xffffffffu, acc.y, off);
        acc.z += __shfl_xor_sync(0xffffffffu, acc.z, off);
        acc.w += __shfl_xor_sync(0xffffffffu, acc.w, off);
    }
    if (lane == 0) {
        float mu = acc.x + bh[0];
        float v  = softplus_(acc.y + bh[1]) + 1e-6f;
        float a  = softplus_(acc.z + bh[2]) + 1.0f + 1e-6f;
        float b  = softplus_(acc.w + bh[3]) + 1e-6f;
        out[outOff + 0 * N + row] = mu;
        out[outOff + 1 * N + row] = v;
        out[outOff + 2 * N + row] = a;
        out[outOff + 3 * N + row] = b;
        if (Gbuf) {
            float u0  = b / fmaxf(a - 1.0f, 1e-8f);
            float sig = 1.0f / (1.0f + expf(-u0));
            Gbuf[row] = 1.0f - gamp[0] * sig;
        }
    }
}

// ---------------- fused softmax stats + in-place gated rescale ---------------
// One block per row: compute m_i, Z, W; then rewrite the row as
// S <- tf32( exp(S-m) * G_j * s_i ),  s_i = (G_i/Z)/max(G_i*W/Z, 1e-8).
__global__ void softmax_fused(float* __restrict__ S, const float* __restrict__ G,
                              int N)
{
    const int row = blockIdx.x;
    float* s = S + (size_t)row * N;
    float m = -INFINITY, Z = 0.f, W = 0.f;
    for (int j = threadIdx.x * 4; j < N; j += 1024) {
        float4 x = *(const float4*)(s + j);
        float4 g = *(const float4*)(G + j);
        float xv[4] = {x.x, x.y, x.z, x.w};
        float gv[4] = {g.x, g.y, g.z, g.w};
#pragma unroll
        for (int q = 0; q < 4; q++) {
            float xx = xv[q];
            if (xx > m) {
                float e = expf(m - xx);
                Z *= e; W *= e; m = xx;
            }
            float p = expf(xx - m);
            Z += p; W = fmaf(p, gv[q], W);
        }
    }
    __shared__ float sm[256], sZ[256], sW[256];
    sm[threadIdx.x] = m; sZ[threadIdx.x] = Z; sW[threadIdx.x] = W;
    __syncthreads();
    for (int off = 128; off > 0; off >>= 1) {
        if (threadIdx.x < off) {
            float m1 = sm[threadIdx.x],       Z1 = sZ[threadIdx.x],       W1 = sW[threadIdx.x];
            float m2 = sm[threadIdx.x + off], Z2 = sZ[threadIdx.x + off], W2 = sW[threadIdx.x + off];
            float mn = fmaxf(m1, m2);
            float e1 = expf(m1 - mn), e2 = expf(m2 - mn);
            sm[threadIdx.x] = mn;
            sZ[threadIdx.x] = Z1 * e1 + Z2 * e2;
            sW[threadIdx.x] = W1 * e1 + W2 * e2;
        }
        __syncthreads();
    }
    const float mF = sm[0], ZF = sZ[0], WF = sW[0];
    const float Gi = G[row];
    const float rowsum = Gi * WF / ZF;
    const float sc = (Gi / ZF) / fmaxf(rowsum, 1e-8f);

    for (int j = threadIdx.x * 4; j < N; j += 1024) {
        float4 v = *(float4*)(s + j);
        float4 g = *(const float4*)(G + j);
        v.x = tfround(expf(v.x - mF) * g.x * sc);
        v.y = tfround(expf(v.y - mF) * g.y * sc);
        v.z = tfround(expf(v.z - mF) * g.z * sc);
        v.w = tfround(expf(v.w - mF) * g.w * sc);
        *(float4*)(s + j) = v;
    }
}

// ---------------- launcher ---------------------------------------------------
extern "C" void kernel_launch(void* const* d_in, const int* in_sizes, int n_in,
                              void* d_out, int out_size)
{
    (void)in_sizes; (void)n_in; (void)out_size;

    const float* X    = (const float*)d_in[0];
    const float* Wq   = (const float*)d_in[1];
    const float* Wk   = (const float*)d_in[2];
    const float* Wg   = (const float*)d_in[3];
    const float* bg   = (const float*)d_in[4];
    const float* gam  = (const float*)d_in[5];
    const float* ihW1 = (const float*)d_in[6];
    const float* ihb1 = (const float*)d_in[7];
    const float* ihW2 = (const float*)d_in[8];
    const float* ihb2 = (const float*)d_in[9];
    const float* ihWh = (const float*)d_in[10];
    const float* ihbh = (const float*)d_in[11];
    const float* fhW1 = (const float*)d_in[12];
    const float* fhb1 = (const float*)d_in[13];
    const float* fhW2 = (const float*)d_in[14];
    const float* fhb2 = (const float*)d_in[15];
    const float* fhWh = (const float*)d_in[16];
    const float* fhbh = (const float*)d_in[17];
    float* out = (float*)d_out;

    float *S, *Q, *Kp, *V, *Y, *H1b, *H2b, *G;
    float *Xtf, *Wqt, *Wkt, *Wgt, *W1a, *W2a, *W1b, *W2b;
    cudaGetSymbolAddress((void**)&S,   g_S);
    cudaGetSymbolAddress((void**)&Q,   g_Q);
    cudaGetSymbolAddress((void**)&Kp,  g_K);
    cudaGetSymbolAddress((void**)&V,   g_V);
    cudaGetSymbolAddress((void**)&Y,   g_Y);
    cudaGetSymbolAddress((void**)&H1b, g_H1);
    cudaGetSymbolAddress((void**)&H2b, g_H2);
    cudaGetSymbolAddress((void**)&G,   g_G);
    cudaGetSymbolAddress((void**)&Xtf, g_Xtf);
    cudaGetSymbolAddress((void**)&Wqt, g_Wqt);
    cudaGetSymbolAddress((void**)&Wkt, g_Wkt);
    cudaGetSymbolAddress((void**)&Wgt, g_Wgt);
    cudaGetSymbolAddress((void**)&W1a, g_W1a);
    cudaGetSymbolAddress((void**)&W2a, g_W2a);
    cudaGetSymbolAddress((void**)&W1b, g_W1b);
    cudaGetSymbolAddress((void**)&W2b, g_W2b);

    const int N = NN_, D = DD_, H1 = HH1_, H2 = HH2_;
    const float invSqrtD = 1.0f / sqrtf((float)D);

    // dynamic smem sizes: 4 stages
    constexpr int SMEM_T  = 4 * (128 * 20 + 128 * 20) * 4;   // TRANSB     (81920 B)
    constexpr int SMEM_NT = 4 * (128 * 20 + 16 * 136) * 4;   // non-TRANSB (75776 B)
    cudaFuncSetAttribute(tgemm<true , 0, false>, cudaFuncAttributeMaxDynamicSharedMemorySize, SMEM_T);
    cudaFuncSetAttribute(tgemm<false, 0, true >, cudaFuncAttributeMaxDynamicSharedMemorySize, SMEM_NT);
    cudaFuncSetAttribute(tgemm<false, 1, true >, cudaFuncAttributeMaxDynamicSharedMemorySize, SMEM_NT);
    cudaFuncSetAttribute(tgemm<false, 1, false>, cudaFuncAttributeMaxDynamicSharedMemorySize, SMEM_NT);
    cudaFuncSetAttribute(tgemm<false, 2, true >, cudaFuncAttributeMaxDynamicSharedMemorySize, SMEM_NT);

    // ---- tf32 rounding of inputs used as GEMM operands ----
    cvt_tf32_kernel<<<(N * D) / 1024, 256>>>(X, Xtf);
    cvt_tf32_kernel<<<(D * D) / 1024, 256>>>(Wq, Wqt);
    cvt_tf32_kernel<<<(D * D) / 1024, 256>>>(Wk, Wkt);
    cvt_tf32_kernel<<<(D * D) / 1024, 256>>>(Wg, Wgt);
    cvt_tf32_kernel<<<(D * H1) / 1024, 256>>>(ihW1, W1a);
    cvt_tf32_kernel<<<(H1 * H2) / 1024, 256>>>(ihW2, W2a);
    cvt_tf32_kernel<<<(D * H1) / 1024, 256>>>(fhW1, W1b);
    cvt_tf32_kernel<<<(H1 * H2) / 1024, 256>>>(fhW2, W2b);

    // ---- head 1 on X -> m0,v0,a0,b0 (out[0..4N)) and gate G ----
    tgemm<false, 1, true ><<<dim3(H1 / 128, N / 128), 256, SMEM_NT>>>(Xtf, W1a, H1b, N, H1, D,  ihb1, nullptr, 1.0f);
    tgemm<false, 1, false><<<dim3(H2 / 128, N / 128), 256, SMEM_NT>>>(H1b, W2a, H2b, N, H2, H1, ihb2, nullptr, 1.0f);
    head_final<<<N / 8, 256>>>(H2b, ihWh, ihbh, out, 0, G, gam, N);

    // ---- projections (tf32-rounded outputs feed the attention GEMMs) ----
    tgemm<false, 0, true><<<dim3(D / 128, N / 128), 256, SMEM_NT>>>(Xtf, Wqt, Q,  N, D, D, nullptr, nullptr, 1.0f);
    tgemm<false, 0, true><<<dim3(D / 128, N / 128), 256, SMEM_NT>>>(Xtf, Wkt, Kp, N, D, D, nullptr, nullptr, 1.0f);
    tgemm<false, 0, true><<<dim3(D / 128, N / 128), 256, SMEM_NT>>>(Xtf, Wgt, V,  N, D, D, nullptr, nullptr, 1.0f);

    // ---- S = Q K^T / sqrt(D) ----
    tgemm<true, 0, false><<<dim3(N / 128, N / 128), 256, SMEM_T>>>(Q, Kp, S, N, N, D, nullptr, nullptr, invSqrtD);

    // ---- fused softmax stats + gated row normalization (tf32 out) ----
    softmax_fused<<<N, 256>>>(S, G, N);

    // ---- Y = tf32(X + gelu(P' @ V + bg)) ----
    tgemm<false, 2, true><<<dim3(D / 128, N / 128), 256, SMEM_NT>>>(S, V, Y, N, D, N, bg, X, 1.0f);

    // ---- head 2 on Y -> mu,v,al,be (out[4N..8N)) ----
    tgemm<false, 1, true ><<<dim3(H1 / 128, N / 128), 256, SMEM_NT>>>(Y,   W1b, H1b, N, H1, D,  fhb1, nullptr, 1.0f);
    tgemm<false, 1, false><<<dim3(H2 / 128, N / 128), 256, SMEM_NT>>>(H1b, W2b, H2b, N, H2, H1, fhb2, nullptr, 1.0f);
    head_final<<<N / 8, 256>>>(H2b, fhWh, fhbh, out, 4 * N, nullptr, gam, N);
}

// round 14
// speedup vs baseline: 1.9222x; 1.4681x over previous
#include <cuda_runtime.h>
#include <cuda_fp16.h>
#include <cstdint>
#include <cmath>

// Problem constants
#define NN_  8192
#define DD_  768
#define HH1_ 512
#define HH2_ 256

// ---------------- device scratch (static globals: allocation-guard legal) ----
__device__ float  g_S  [67108864];            // 8192*8192 fp32 attention scores
__device__ __half g_Ph [67108864];            // P' fp16 (post-softmax, gated, scaled)
__device__ __half g_Xh [NN_ * DD_];
__device__ __half g_Qh [NN_ * DD_];
__device__ __half g_Kh [NN_ * DD_];
__device__ __half g_Vt [DD_ * NN_];           // V^T  [768][8192]
__device__ __half g_Yh [NN_ * DD_];
__device__ __half g_H1h[NN_ * HH1_];
__device__ __half g_H2h[NN_ * HH2_];
__device__ float  g_G  [NN_];
__device__ __half g_WqT[DD_ * DD_];
__device__ __half g_WkT[DD_ * DD_];
__device__ __half g_WgT[DD_ * DD_];
__device__ __half g_W1aT[HH1_ * DD_];
__device__ __half g_W2aT[HH2_ * HH1_];
__device__ __half g_W1bT[HH1_ * DD_];
__device__ __half g_W2bT[HH2_ * HH1_];

// ---------------- math helpers ---------------------------------------------
__device__ __forceinline__ float gelu_exact(float x) {
    return 0.5f * x * (1.0f + erff(x * 0.70710678118654752440f));
}
__device__ __forceinline__ float softplus_(float x) {
    return fmaxf(x, 0.0f) + log1pf(expf(-fabsf(x)));
}
__device__ __forceinline__ void mma_f16(float* c, const unsigned* a, const unsigned* b) {
    asm volatile(
        "mma.sync.aligned.m16n8k16.row.col.f32.f16.f16.f32 "
        "{%0,%1,%2,%3}, {%4,%5,%6,%7}, {%8,%9}, {%0,%1,%2,%3};"
        : "+f"(c[0]), "+f"(c[1]), "+f"(c[2]), "+f"(c[3])
        : "r"(a[0]), "r"(a[1]), "r"(a[2]), "r"(a[3]), "r"(b[0]), "r"(b[1]));
}
__device__ __forceinline__ void cp_async16(unsigned dst, const void* src) {
    unsigned long long gsrc = __cvta_generic_to_global(src);
    asm volatile("cp.async.cg.shared.global [%0], [%1], 16;" :: "r"(dst), "l"(gsrc) : "memory");
}
__device__ __forceinline__ unsigned smem_addr(const void* p) {
    return (unsigned)__cvta_generic_to_shared(p);
}

// ---------------- fp32 -> fp16 elementwise ----------------------------------
__global__ void cvt_half_kernel(const float* __restrict__ in, __half* __restrict__ outp) {
    const int i = (blockIdx.x * 256 + threadIdx.x) * 4;
    float4 v = *(const float4*)(in + i);
    *(__half2*)(outp + i)     = __floats2half2_rn(v.x, v.y);
    *(__half2*)(outp + i + 2) = __floats2half2_rn(v.z, v.w);
}

// ---------------- fp32 [R][C] -> fp16 transposed [C][R] ----------------------
__global__ void cvtT_half_kernel(const float* __restrict__ in, __half* __restrict__ outp,
                                 int R, int C) {
    __shared__ float t[32][33];
    const int cb = blockIdx.x * 32, rb = blockIdx.y * 32;
    for (int i = threadIdx.y; i < 32; i += 8)
        t[i][threadIdx.x] = in[(size_t)(rb + i) * C + cb + threadIdx.x];
    __syncthreads();
    for (int i = threadIdx.y; i < 32; i += 8)
        outp[(size_t)(cb + i) * R + rb + threadIdx.x] = __float2half(t[threadIdx.x][i]);
}

// ============================================================================
// 128x128x16 FP16 tensor-core GEMM, all-TRANSB form, 4-stage cp.async pipeline.
// A: [M,K] half row-major (K-major); B: [Nn_total,K] half row-major (K-major).
// C = epi( scale * A @ B^T )
//   EPI 0: C = acc*scale
//   EPI 1: C = gelu(acc + bias[col])
//   EPI 2: C = addsrc[row,col] + gelu(acc + bias[col])    (addsrc fp32)
//   HOUT : C stored as __half (else float)
//   TSTORE: C stored transposed, C[col*M + row] (half only)
// Requires: M%128==0, Nn%128==0, K%16==0, K/16 >= 3.
// Smem: per stage A[128][12] uints (half2-packed k-pairs) + B same. Pitch 12
// words is 16B-aligned per row and conflict-free for fragment reads.
// ============================================================================
template<int EPI, bool HOUT, bool TSTORE>
__global__ __launch_bounds__(256)
void hgemm(const __half* __restrict__ A, const __half* __restrict__ B,
           void* __restrict__ Cv, int M, int Nn, int K,
           const float* __restrict__ bias, const float* __restrict__ addsrc,
           float scale)
{
    constexpr int KT = 16, NSTAGE = 4;
    constexpr int TW = 128 * 12;              // words per (A or B) stage
    extern __shared__ unsigned sm[];
    unsigned* AsBase = sm;                    // [NSTAGE][128][12]
    unsigned* BsBase = sm + NSTAGE * TW;

    const int tid  = threadIdx.x;
    const int lane = tid & 31;
    const int warp = tid >> 5;
    const int warpM = (warp & 1) * 64;
    const int warpN = (warp >> 1) * 32;
    const int rowBase = blockIdx.y * 128, colBase = blockIdx.x * 128;

    // loader: one 16B chunk per matrix per thread: row = tid>>1 (0..127), seg = tid&1
    const int ldRow = tid >> 1;
    const int ldSeg = tid & 1;                 // k halves 8*seg .. 8*seg+7
    const __half* gA = A + (size_t)(rowBase + ldRow) * K + ldSeg * 8;
    const __half* gB = B + (size_t)(colBase + ldRow) * K + ldSeg * 8;
    const unsigned stOff = (ldRow * 12 + ldSeg * 4) * 4;   // bytes

    auto load_tile = [&](int t, int s) {
        cp_async16(smem_addr(AsBase + s * TW) + stOff, gA + t * KT);
        cp_async16(smem_addr(BsBase + s * TW) + stOff, gB + t * KT);
    };

    float acc[4][4][4];
#pragma unroll
    for (int i = 0; i < 4; i++)
#pragma unroll
        for (int j = 0; j < 4; j++)
#pragma unroll
            for (int q = 0; q < 4; q++) acc[i][j][q] = 0.0f;

    const int ntiles = K / KT;

#pragma unroll
    for (int s = 0; s < NSTAGE - 1; s++) {
        load_tile(s, s);
        asm volatile("cp.async.commit_group;" ::: "memory");
    }

    const int r0 = lane >> 2;      // 0..7
    const int c0 = lane & 3;       // 0..3 (k-pair index)

    for (int t = 0; t < ntiles; t++) {
        asm volatile("cp.async.wait_group 2;" ::: "memory");
        __syncthreads();

        const int st = t & (NSTAGE - 1);
        const unsigned* As = AsBase + st * TW;
        const unsigned* Bs = BsBase + st * TW;

        unsigned af[4][4];
#pragma unroll
        for (int i = 0; i < 4; i++) {
            const int m0 = warpM + i * 16;
            af[i][0] = As[(m0 + r0)     * 12 + c0    ];
            af[i][1] = As[(m0 + r0 + 8) * 12 + c0    ];
            af[i][2] = As[(m0 + r0)     * 12 + c0 + 4];
            af[i][3] = As[(m0 + r0 + 8) * 12 + c0 + 4];
        }
        unsigned bf[4][2];
#pragma unroll
        for (int j = 0; j < 4; j++) {
            const int n0 = warpN + j * 8;
            bf[j][0] = Bs[(n0 + r0) * 12 + c0    ];
            bf[j][1] = Bs[(n0 + r0) * 12 + c0 + 4];
        }
#pragma unroll
        for (int i = 0; i < 4; i++)
#pragma unroll
            for (int j = 0; j < 4; j++)
                mma_f16(acc[i][j], af[i], bf[j]);

        const int tn = t + NSTAGE - 1;
        if (tn < ntiles) load_tile(tn, tn & (NSTAGE - 1));
        asm volatile("cp.async.commit_group;" ::: "memory");
    }

    // epilogue: fragment m16n8 -> c0,c1 at (r0, 2c), c2,c3 at (r0+8, 2c)
    float* Cf = (float*)Cv;
    __half* Ch = (__half*)Cv;
    const int cc = (lane & 3) * 2;
#pragma unroll
    for (int i = 0; i < 4; i++) {
        const int gr = rowBase + warpM + i * 16 + r0;
#pragma unroll
        for (int j = 0; j < 4; j++) {
            const int gc = colBase + warpN + j * 8 + cc;
#pragma unroll
            for (int half_ = 0; half_ < 2; half_++) {
                const int row = gr + half_ * 8;
                float v0 = acc[i][j][half_ * 2 + 0] * scale;
                float v1 = acc[i][j][half_ * 2 + 1] * scale;
                if (EPI == 1) {
                    v0 = gelu_exact(v0 + bias[gc]);
                    v1 = gelu_exact(v1 + bias[gc + 1]);
                } else if (EPI == 2) {
                    const float* ap = addsrc + (size_t)row * Nn + gc;
                    v0 = ap[0] + gelu_exact(v0 + bias[gc]);
                    v1 = ap[1] + gelu_exact(v1 + bias[gc + 1]);
                }
                if (TSTORE) {
                    Ch[(size_t)gc * M + row]       = __float2half(v0);
                    Ch[(size_t)(gc + 1) * M + row] = __float2half(v1);
                } else if (HOUT) {
                    *(__half2*)(Ch + (size_t)row * Nn + gc) = __floats2half2_rn(v0, v1);
                } else {
                    *(float2*)(Cf + (size_t)row * Nn + gc) = make_float2(v0, v1);
                }
            }
        }
    }
}

// ---------------- NIG head final ---------------------------------------------
__global__ void head_final(const __half* __restrict__ H2, const float* __restrict__ Wh,
                           const float* __restrict__ bh, float* __restrict__ out,
                           int outOff, float* __restrict__ Gbuf,
                           const float* __restrict__ gamp, int N)
{
    const int warp = threadIdx.x >> 5, lane = threadIdx.x & 31;
    const int row = blockIdx.x * 8 + warp;

    float4 acc = make_float4(0.f, 0.f, 0.f, 0.f);
    const __half* h = H2 + (size_t)row * HH2_ + lane * 8;
#pragma unroll
    for (int i = 0; i < 8; i++) {
        float hv = __half2float(h[i]);
        float4 w = *(const float4*)&Wh[(lane * 8 + i) * 4];
        acc.x = fmaf(hv, w.x, acc.x);
        acc.y = fmaf(hv, w.y, acc.y);
        acc.z = fmaf(hv, w.z, acc.z);
        acc.w = fmaf(hv, w.w, acc.w);
    }
#pragma unroll
    for (int off = 16; off > 0; off >>= 1) {
        acc.x += __shfl_xor_sync(0xffffffffu, acc.x, off);
        acc.y += __shfl_xor_sync(0xffffffffu, acc.y, off);
        acc.z += __shfl_xor_sync(0xffffffffu, acc.z, off);
        acc.w += __shfl_xor_sync(0xffffffffu, acc.w, off);
    }
    if (lane == 0) {
        float mu = acc.x + bh[0];
        float v  = softplus_(acc.y + bh[1]) + 1e-6f;
        float a  = softplus_(acc.z + bh[2]) + 1.0f + 1e-6f;
        float b  = softplus_(acc.w + bh[3]) + 1e-6f;
        out[outOff + 0 * N + row] = mu;
        out[outOff + 1 * N + row] = v;
        out[outOff + 2 * N + row] = a;
        out[outOff + 3 * N + row] = b;
        if (Gbuf) {
            float u0  = b / fmaxf(a - 1.0f, 1e-8f);
            float sig = 1.0f / (1.0f + expf(-u0));
            Gbuf[row] = 1.0f - gamp[0] * sig;
        }
    }
}

// ---------------- fused softmax stats + gated rescale -> fp16 P' -------------
// One block per row: m_i, Z, W over fp32 S; then P'[i,j] = half(exp(S-m)*G_j*s_i)
// with s_i = (G_i/Z)/max(G_i*W/Z, 1e-8).
__global__ void softmax_fused(const float* __restrict__ S, __half* __restrict__ P,
                              const float* __restrict__ G, int N)
{
    const int row = blockIdx.x;
    const float* s = S + (size_t)row * N;
    __half* p = P + (size_t)row * N;
    float m = -INFINITY, Z = 0.f, W = 0.f;
    for (int j = threadIdx.x * 4; j < N; j += 1024) {
        float4 x = *(const float4*)(s + j);
        float4 g = *(const float4*)(G + j);
        float xv[4] = {x.x, x.y, x.z, x.w};
        float gv[4] = {g.x, g.y, g.z, g.w};
#pragma unroll
        for (int q = 0; q < 4; q++) {
            float xx = xv[q];
            if (xx > m) {
                float e = expf(m - xx);
                Z *= e; W *= e; m = xx;
            }
            float pq = expf(xx - m);
            Z += pq; W = fmaf(pq, gv[q], W);
        }
    }
    __shared__ float sm[256], sZ[256], sW[256];
    sm[threadIdx.x] = m; sZ[threadIdx.x] = Z; sW[threadIdx.x] = W;
    __syncthreads();
    for (int off = 128; off > 0; off >>= 1) {
        if (threadIdx.x < off) {
            float m1 = sm[threadIdx.x],       Z1 = sZ[threadIdx.x],       W1 = sW[threadIdx.x];
            float m2 = sm[threadIdx.x + off], Z2 = sZ[threadIdx.x + off], W2 = sW[threadIdx.x + off];
            float mn = fmaxf(m1, m2);
            float e1 = expf(m1 - mn), e2 = expf(m2 - mn);
            sm[threadIdx.x] = mn;
            sZ[threadIdx.x] = Z1 * e1 + Z2 * e2;
            sW[threadIdx.x] = W1 * e1 + W2 * e2;
        }
        __syncthreads();
    }
    const float mF = sm[0], ZF = sZ[0], WF = sW[0];
    const float Gi = G[row];
    const float rowsum = Gi * WF / ZF;
    const float sc = (Gi / ZF) / fmaxf(rowsum, 1e-8f);

    for (int j = threadIdx.x * 4; j < N; j += 1024) {
        float4 v = *(const float4*)(s + j);
        float4 g = *(const float4*)(G + j);
        *(__half2*)(p + j)     = __floats2half2_rn(expf(v.x - mF) * g.x * sc, expf(v.y - mF) * g.y * sc);
        *(__half2*)(p + j + 2) = __floats2half2_rn(expf(v.z - mF) * g.z * sc, expf(v.w - mF) * g.w * sc);
    }
}

// ---------------- launcher ---------------------------------------------------
extern "C" void kernel_launch(void* const* d_in, const int* in_sizes, int n_in,
                              void* d_out, int out_size)
{
    (void)in_sizes; (void)n_in; (void)out_size;

    const float* X    = (const float*)d_in[0];
    const float* Wq   = (const float*)d_in[1];
    const float* Wk   = (const float*)d_in[2];
    const float* Wg   = (const float*)d_in[3];
    const float* bg   = (const float*)d_in[4];
    const float* gam  = (const float*)d_in[5];
    const float* ihW1 = (const float*)d_in[6];
    const float* ihb1 = (const float*)d_in[7];
    const float* ihW2 = (const float*)d_in[8];
    const float* ihb2 = (const float*)d_in[9];
    const float* ihWh = (const float*)d_in[10];
    const float* ihbh = (const float*)d_in[11];
    const float* fhW1 = (const float*)d_in[12];
    const float* fhb1 = (const float*)d_in[13];
    const float* fhW2 = (const float*)d_in[14];
    const float* fhb2 = (const float*)d_in[15];
    const float* fhWh = (const float*)d_in[16];
    const float* fhbh = (const float*)d_in[17];
    float* out = (float*)d_out;

    float *S, *G;
    __half *Ph, *Xh, *Qh, *Kh, *Vt, *Yh, *H1h, *H2h;
    __half *WqT, *WkT, *WgT, *W1aT, *W2aT, *W1bT, *W2bT;
    cudaGetSymbolAddress((void**)&S,   g_S);
    cudaGetSymbolAddress((void**)&G,   g_G);
    cudaGetSymbolAddress((void**)&Ph,  g_Ph);
    cudaGetSymbolAddress((void**)&Xh,  g_Xh);
    cudaGetSymbolAddress((void**)&Qh,  g_Qh);
    cudaGetSymbolAddress((void**)&Kh,  g_Kh);
    cudaGetSymbolAddress((void**)&Vt,  g_Vt);
    cudaGetSymbolAddress((void**)&Yh,  g_Yh);
    cudaGetSymbolAddress((void**)&H1h, g_H1h);
    cudaGetSymbolAddress((void**)&H2h, g_H2h);
    cudaGetSymbolAddress((void**)&WqT, g_WqT);
    cudaGetSymbolAddress((void**)&WkT, g_WkT);
    cudaGetSymbolAddress((void**)&WgT, g_WgT);
    cudaGetSymbolAddress((void**)&W1aT, g_W1aT);
    cudaGetSymbolAddress((void**)&W2aT, g_W2aT);
    cudaGetSymbolAddress((void**)&W1bT, g_W1bT);
    cudaGetSymbolAddress((void**)&W2bT, g_W2bT);

    const int N = NN_, D = DD_, H1 = HH1_, H2 = HH2_;
    const float invSqrtD = 1.0f / sqrtf((float)D);

    constexpr int SMEM_H = 4 * 2 * 128 * 12 * 4;   // 49152 B
    cudaFuncSetAttribute(hgemm<0, false, false>, cudaFuncAttributeMaxDynamicSharedMemorySize, SMEM_H);
    cudaFuncSetAttribute(hgemm<0, true , false>, cudaFuncAttributeMaxDynamicSharedMemorySize, SMEM_H);
    cudaFuncSetAttribute(hgemm<0, true , true >, cudaFuncAttributeMaxDynamicSharedMemorySize, SMEM_H);
    cudaFuncSetAttribute(hgemm<1, true , false>, cudaFuncAttributeMaxDynamicSharedMemorySize, SMEM_H);
    cudaFuncSetAttribute(hgemm<2, true , false>, cudaFuncAttributeMaxDynamicSharedMemorySize, SMEM_H);

    // ---- fp16 conversions (X elementwise; weights transposed) ----
    cvt_half_kernel<<<(N * D) / 1024, 256>>>(X, Xh);
    dim3 tb(32, 8);
    cvtT_half_kernel<<<dim3(D / 32, D / 32), tb>>>(Wq, WqT, D, D);
    cvtT_half_kernel<<<dim3(D / 32, D / 32), tb>>>(Wk, WkT, D, D);
    cvtT_half_kernel<<<dim3(D / 32, D / 32), tb>>>(Wg, WgT, D, D);
    cvtT_half_kernel<<<dim3(H1 / 32, D / 32), tb>>>(ihW1, W1aT, D, H1);
    cvtT_half_kernel<<<dim3(H2 / 32, H1 / 32), tb>>>(ihW2, W2aT, H1, H2);
    cvtT_half_kernel<<<dim3(H1 / 32, D / 32), tb>>>(fhW1, W1bT, D, H1);
    cvtT_half_kernel<<<dim3(H2 / 32, H1 / 32), tb>>>(fhW2, W2bT, H1, H2);

    // ---- head 1 on X -> m0,v0,a0,b0 (out[0..4N)) and gate G ----
    hgemm<1, true, false><<<dim3(H1 / 128, N / 128), 256, SMEM_H>>>(Xh,  W1aT, H1h, N, H1, D,  ihb1, nullptr, 1.0f);
    hgemm<1, true, false><<<dim3(H2 / 128, N / 128), 256, SMEM_H>>>(H1h, W2aT, H2h, N, H2, H1, ihb2, nullptr, 1.0f);
    head_final<<<N / 8, 256>>>(H2h, ihWh, ihbh, out, 0, G, gam, N);

    // ---- projections: Qh, Kh row-major; V stored transposed (Vt) ----
    hgemm<0, true, false><<<dim3(D / 128, N / 128), 256, SMEM_H>>>(Xh, WqT, Qh, N, D, D, nullptr, nullptr, 1.0f);
    hgemm<0, true, false><<<dim3(D / 128, N / 128), 256, SMEM_H>>>(Xh, WkT, Kh, N, D, D, nullptr, nullptr, 1.0f);
    hgemm<0, true, true ><<<dim3(D / 128, N / 128), 256, SMEM_H>>>(Xh, WgT, Vt, N, D, D, nullptr, nullptr, 1.0f);

    // ---- S = Q K^T / sqrt(D)  (fp32 out) ----
    hgemm<0, false, false><<<dim3(N / 128, N / 128), 256, SMEM_H>>>(Qh, Kh, S, N, N, D, nullptr, nullptr, invSqrtD);

    // ---- fused softmax stats + gated row normalization -> fp16 P' ----
    softmax_fused<<<N, 256>>>(S, Ph, G, N);

    // ---- Y = X + gelu(P' @ V + bg)  (A=Ph [N,N], B=Vt [D][N] K-major) ----
    hgemm<2, true, false><<<dim3(D / 128, N / 128), 256, SMEM_H>>>(Ph, Vt, Yh, N, D, N, bg, X, 1.0f);

    // ---- head 2 on Y -> mu,v,al,be (out[4N..8N)) ----
    hgemm<1, true, false><<<dim3(H1 / 128, N / 128), 256, SMEM_H>>>(Yh,  W1bT, H1h, N, H1, D,  fhb1, nullptr, 1.0f);
    hgemm<1, true, false><<<dim3(H2 / 128, N / 128), 256, SMEM_H>>>(H1h, W2bT, H2h, N, H2, H1, fhb2, nullptr, 1.0f);
    head_final<<<N / 8, 256>>>(H2h, fhWh, fhbh, out, 4 * N, nullptr, gam, N);
}

// round 16
// speedup vs baseline: 2.1678x; 1.1277x over previous
#include <cuda_runtime.h>
#include <cuda_fp16.h>
#include <cstdint>
#include <cmath>

// Problem constants
#define NN_  8192
#define DD_  768
#define HH1_ 512
#define HH2_ 256

// ---------------- device scratch (static globals: allocation-guard legal) ----
__device__ float  g_S  [67108864];            // 8192*8192 fp32 attention scores
__device__ __half g_Ph [67108864];            // P' fp16 (post-softmax, gated, scaled)
__device__ __half g_Xh [NN_ * DD_];
__device__ __half g_Qh [NN_ * DD_];
__device__ __half g_Kh [NN_ * DD_];
__device__ __half g_Vt [DD_ * NN_];           // V^T  [768][8192]
__device__ __half g_Yh [NN_ * DD_];
__device__ __half g_H1h[NN_ * HH1_];
__device__ __half g_H2h[NN_ * HH2_];
__device__ float  g_G  [NN_];
__device__ __half g_WqT[DD_ * DD_];
__device__ __half g_WkT[DD_ * DD_];
__device__ __half g_WgT[DD_ * DD_];
__device__ __half g_W1aT[HH1_ * DD_];
__device__ __half g_W2aT[HH2_ * HH1_];
__device__ __half g_W1bT[HH1_ * DD_];
__device__ __half g_W2bT[HH2_ * HH1_];

// ---------------- math helpers ---------------------------------------------
__device__ __forceinline__ float gelu_exact(float x) {
    return 0.5f * x * (1.0f + erff(x * 0.70710678118654752440f));
}
__device__ __forceinline__ float softplus_(float x) {
    return fmaxf(x, 0.0f) + log1pf(expf(-fabsf(x)));
}
__device__ __forceinline__ void mma_f16(float* c, const unsigned* a, const unsigned* b) {
    asm volatile(
        "mma.sync.aligned.m16n8k16.row.col.f32.f16.f16.f32 "
        "{%0,%1,%2,%3}, {%4,%5,%6,%7}, {%8,%9}, {%0,%1,%2,%3};"
        : "+f"(c[0]), "+f"(c[1]), "+f"(c[2]), "+f"(c[3])
        : "r"(a[0]), "r"(a[1]), "r"(a[2]), "r"(a[3]), "r"(b[0]), "r"(b[1]));
}
__device__ __forceinline__ void ldsm_x4(unsigned& r0, unsigned& r1, unsigned& r2, unsigned& r3,
                                        unsigned addr) {
    asm volatile("ldmatrix.sync.aligned.m8n8.x4.shared.b16 {%0,%1,%2,%3}, [%4];"
                 : "=r"(r0), "=r"(r1), "=r"(r2), "=r"(r3) : "r"(addr));
}
__device__ __forceinline__ void cp_async16(unsigned dst, const void* src) {
    unsigned long long gsrc = __cvta_generic_to_global(src);
    asm volatile("cp.async.cg.shared.global [%0], [%1], 16;" :: "r"(dst), "l"(gsrc) : "memory");
}
__device__ __forceinline__ unsigned smem_addr(const void* p) {
    return (unsigned)__cvta_generic_to_shared(p);
}

// ---------------- fp32 -> fp16 elementwise ----------------------------------
__global__ void cvt_half_kernel(const float* __restrict__ in, __half* __restrict__ outp) {
    const int i = (blockIdx.x * 256 + threadIdx.x) * 4;
    float4 v = *(const float4*)(in + i);
    *(__half2*)(outp + i)     = __floats2half2_rn(v.x, v.y);
    *(__half2*)(outp + i + 2) = __floats2half2_rn(v.z, v.w);
}

// ---------------- fp32 [R][C] -> fp16 transposed [C][R] ----------------------
__global__ void cvtT_half_kernel(const float* __restrict__ in, __half* __restrict__ outp,
                                 int R, int C) {
    __shared__ float t[32][33];
    const int cb = blockIdx.x * 32, rb = blockIdx.y * 32;
    for (int i = threadIdx.y; i < 32; i += 8)
        t[i][threadIdx.x] = in[(size_t)(rb + i) * C + cb + threadIdx.x];
    __syncthreads();
    for (int i = threadIdx.y; i < 32; i += 8)
        outp[(size_t)(cb + i) * R + rb + threadIdx.x] = __float2half(t[threadIdx.x][i]);
}

// ============================================================================
// 128x128x16 FP16 tensor-core GEMM, all-TRANSB form, 4-stage cp.async pipeline,
// ldmatrix fragment loads.
// A: [M,K] half row-major (K-major); B: [Nn_total,K] half row-major (K-major).
// C = epi( scale * A @ B^T )
//   EPI 0: C = acc*scale
//   EPI 1: C = gelu(acc + bias[col])
//   EPI 2: C = addsrc[row,col] + gelu(acc + bias[col])    (addsrc fp32)
//   HOUT : C stored as __half (else float)
//   TSTORE: C stored transposed, C[col*M + row] (half only)
// Requires: M%128==0, Nn%128==0, K%16==0, K/16 >= 3.
// Smem: per stage A[128][12] uints (8 payload words + 4 pad) + B same.
// Pitch 12 words => ldmatrix phases cover all 32 banks (conflict-free).
// ============================================================================
template<int EPI, bool HOUT, bool TSTORE>
__global__ __launch_bounds__(256)
void hgemm(const __half* __restrict__ A, const __half* __restrict__ B,
           void* __restrict__ Cv, int M, int Nn, int K,
           const float* __restrict__ bias, const float* __restrict__ addsrc,
           float scale)
{
    constexpr int KT = 16, NSTAGE = 4;
    constexpr int TW = 128 * 12;              // words per (A or B) stage
    extern __shared__ unsigned sm[];
    unsigned* AsBase = sm;                    // [NSTAGE][128][12]
    unsigned* BsBase = sm + NSTAGE * TW;

    const int tid  = threadIdx.x;
    const int lane = tid & 31;
    const int warp = tid >> 5;
    const int warpM = (warp & 1) * 64;
    const int warpN = (warp >> 1) * 32;
    const int rowBase = blockIdx.y * 128, colBase = blockIdx.x * 128;

    // loader: one 16B chunk per matrix per thread: row = tid>>1, seg = tid&1
    const int ldRow = tid >> 1;
    const int ldSeg = tid & 1;
    const __half* gA = A + (size_t)(rowBase + ldRow) * K + ldSeg * 8;
    const __half* gB = B + (size_t)(colBase + ldRow) * K + ldSeg * 8;
    const unsigned stOff = (ldRow * 12 + ldSeg * 4) * 4;   // bytes

    auto load_tile = [&](int t, int s) {
        cp_async16(smem_addr(AsBase + s * TW) + stOff, gA + t * KT);
        cp_async16(smem_addr(BsBase + s * TW) + stOff, gB + t * KT);
    };

    // ldmatrix per-lane addresses (byte offsets within a stage)
    //  A fragment i: rows warpM + i*16 + (lane&15), k-half = lane>>4
    const unsigned aFragOff = ((warpM + (lane & 15)) * 12 + (lane >> 4) * 4) * 4;
    //  B pair jp: rows warpN + jp*16 + (lane>>4)*8 + (lane&7), k-half = (lane>>3)&1
    const unsigned bFragOff = ((warpN + (lane >> 4) * 8 + (lane & 7)) * 12
                               + ((lane >> 3) & 1) * 4) * 4;
    const unsigned aBaseS = smem_addr(AsBase);
    const unsigned bBaseS = smem_addr(BsBase);

    float acc[4][4][4];
#pragma unroll
    for (int i = 0; i < 4; i++)
#pragma unroll
        for (int j = 0; j < 4; j++)
#pragma unroll
            for (int q = 0; q < 4; q++) acc[i][j][q] = 0.0f;

    const int ntiles = K / KT;

#pragma unroll
    for (int s = 0; s < NSTAGE - 1; s++) {
        load_tile(s, s);
        asm volatile("cp.async.commit_group;" ::: "memory");
    }

    for (int t = 0; t < ntiles; t++) {
        asm volatile("cp.async.wait_group 2;" ::: "memory");
        __syncthreads();

        // issue next tile's loads early (stage t-1 mod 4 is free after the sync)
        const int tn = t + NSTAGE - 1;
        if (tn < ntiles) load_tile(tn, tn & (NSTAGE - 1));
        asm volatile("cp.async.commit_group;" ::: "memory");

        const int st = t & (NSTAGE - 1);
        const unsigned aSt = aBaseS + st * (TW * 4) + aFragOff;
        const unsigned bSt = bBaseS + st * (TW * 4) + bFragOff;

        unsigned af[4][4];
#pragma unroll
        for (int i = 0; i < 4; i++)
            ldsm_x4(af[i][0], af[i][1], af[i][2], af[i][3], aSt + i * (16 * 12 * 4));

        unsigned bf[4][2];
#pragma unroll
        for (int jp = 0; jp < 2; jp++)
            ldsm_x4(bf[2 * jp][0], bf[2 * jp][1], bf[2 * jp + 1][0], bf[2 * jp + 1][1],
                    bSt + jp * (16 * 12 * 4));

#pragma unroll
        for (int i = 0; i < 4; i++)
#pragma unroll
            for (int j = 0; j < 4; j++)
                mma_f16(acc[i][j], af[i], bf[j]);
    }

    // epilogue: fragment m16n8 -> c0,c1 at (r0, 2c), c2,c3 at (r0+8, 2c)
    float* Cf = (float*)Cv;
    __half* Ch = (__half*)Cv;
    const int r0 = lane >> 2;
    const int cc = (lane & 3) * 2;
#pragma unroll
    for (int i = 0; i < 4; i++) {
        const int gr = rowBase + warpM + i * 16 + r0;
#pragma unroll
        for (int j = 0; j < 4; j++) {
            const int gc = colBase + warpN + j * 8 + cc;
#pragma unroll
            for (int half_ = 0; half_ < 2; half_++) {
                const int row = gr + half_ * 8;
                float v0 = acc[i][j][half_ * 2 + 0] * scale;
                float v1 = acc[i][j][half_ * 2 + 1] * scale;
                if (EPI == 1) {
                    v0 = gelu_exact(v0 + bias[gc]);
                    v1 = gelu_exact(v1 + bias[gc + 1]);
                } else if (EPI == 2) {
                    const float* ap = addsrc + (size_t)row * Nn + gc;
                    v0 = ap[0] + gelu_exact(v0 + bias[gc]);
                    v1 = ap[1] + gelu_exact(v1 + bias[gc + 1]);
                }
                if (TSTORE) {
                    Ch[(size_t)gc * M + row]       = __float2half(v0);
                    Ch[(size_t)(gc + 1) * M + row] = __float2half(v1);
                } else if (HOUT) {
                    *(__half2*)(Ch + (size_t)row * Nn + gc) = __floats2half2_rn(v0, v1);
                } else {
                    *(float2*)(Cf + (size_t)row * Nn + gc) = make_float2(v0, v1);
                }
            }
        }
    }
}

// ---------------- NIG head final ---------------------------------------------
__global__ void head_final(const __half* __restrict__ H2, const float* __restrict__ Wh,
                           const float* __restrict__ bh, float* __restrict__ out,
                           int outOff, float* __restrict__ Gbuf,
                           const float* __restrict__ gamp, int N)
{
    const int warp = threadIdx.x >> 5, lane = threadIdx.x & 31;
    const int row = blockIdx.x * 8 + warp;

    float4 acc = make_float4(0.f, 0.f, 0.f, 0.f);
    const __half* h = H2 + (size_t)row * HH2_ + lane * 8;
#pragma unroll
    for (int i = 0; i < 8; i++) {
        float hv = __half2float(h[i]);
        float4 w = *(const float4*)&Wh[(lane * 8 + i) * 4];
        acc.x = fmaf(hv, w.x, acc.x);
        acc.y = fmaf(hv, w.y, acc.y);
        acc.z = fmaf(hv, w.z, acc.z);
        acc.w = fmaf(hv, w.w, acc.w);
    }
#pragma unroll
    for (int off = 16; off > 0; off >>= 1) {
        acc.x += __shfl_xor_sync(0xffffffffu, acc.x, off);
        acc.y += __shfl_xor_sync(0xffffffffu, acc.y, off);
        acc.z += __shfl_xor_sync(0xffffffffu, acc.z, off);
        acc.w += __shfl_xor_sync(0xffffffffu, acc.w, off);
    }
    if (lane == 0) {
        float mu = acc.x + bh[0];
        float v  = softplus_(acc.y + bh[1]) + 1e-6f;
        float a  = softplus_(acc.z + bh[2]) + 1.0f + 1e-6f;
        float b  = softplus_(acc.w + bh[3]) + 1e-6f;
        out[outOff + 0 * N + row] = mu;
        out[outOff + 1 * N + row] = v;
        out[outOff + 2 * N + row] = a;
        out[outOff + 3 * N + row] = b;
        if (Gbuf) {
            float u0  = b / fmaxf(a - 1.0f, 1e-8f);
            float sig = 1.0f / (1.0f + expf(-u0));
            Gbuf[row] = 1.0f - gamp[0] * sig;
        }
    }
}

// ---------------- fused softmax stats + gated rescale -> fp16 P' -------------
__global__ void softmax_fused(const float* __restrict__ S, __half* __restrict__ P,
                              const float* __restrict__ G, int N)
{
    const int row = blockIdx.x;
    const float* s = S + (size_t)row * N;
    __half* p = P + (size_t)row * N;
    float m = -INFINITY, Z = 0.f, W = 0.f;
    for (int j = threadIdx.x * 4; j < N; j += 1024) {
        float4 x = *(const float4*)(s + j);
        float4 g = *(const float4*)(G + j);
        float xv[4] = {x.x, x.y, x.z, x.w};
        float gv[4] = {g.x, g.y, g.z, g.w};
#pragma unroll
        for (int q = 0; q < 4; q++) {
            float xx = xv[q];
            if (xx > m) {
                float e = expf(m - xx);
                Z *= e; W *= e; m = xx;
            }
            float pq = expf(xx - m);
            Z += pq; W = fmaf(pq, gv[q], W);
        }
    }
    __shared__ float sm[256], sZ[256], sW[256];
    sm[threadIdx.x] = m; sZ[threadIdx.x] = Z; sW[threadIdx.x] = W;
    __syncthreads();
    for (int off = 128; off > 0; off >>= 1) {
        if (threadIdx.x < off) {
            float m1 = sm[threadIdx.x],       Z1 = sZ[threadIdx.x],       W1 = sW[threadIdx.x];
            float m2 = sm[threadIdx.x + off], Z2 = sZ[threadIdx.x + off], W2 = sW[threadIdx.x + off];
            float mn = fmaxf(m1, m2);
            float e1 = expf(m1 - mn), e2 = expf(m2 - mn);
            sm[threadIdx.x] = mn;
            sZ[threadIdx.x] = Z1 * e1 + Z2 * e2;
            sW[threadIdx.x] = W1 * e1 + W2 * e2;
        }
        __syncthreads();
    }
    const float mF = sm[0], ZF = sZ[0], WF = sW[0];
    const float Gi = G[row];
    const float rowsum = Gi * WF / ZF;
    const float sc = (Gi / ZF) / fmaxf(rowsum, 1e-8f);

    for (int j = threadIdx.x * 4; j < N; j += 1024) {
        float4 v = *(const float4*)(s + j);
        float4 g = *(const float4*)(G + j);
        *(__half2*)(p + j)     = __floats2half2_rn(expf(v.x - mF) * g.x * sc, expf(v.y - mF) * g.y * sc);
        *(__half2*)(p + j + 2) = __floats2half2_rn(expf(v.z - mF) * g.z * sc, expf(v.w - mF) * g.w * sc);
    }
}

// ---------------- launcher ---------------------------------------------------
extern "C" void kernel_launch(void* const* d_in, const int* in_sizes, int n_in,
                              void* d_out, int out_size)
{
    (void)in_sizes; (void)n_in; (void)out_size;

    const float* X    = (const float*)d_in[0];
    const float* Wq   = (const float*)d_in[1];
    const float* Wk   = (const float*)d_in[2];
    const float* Wg   = (const float*)d_in[3];
    const float* bg   = (const float*)d_in[4];
    const float* gam  = (const float*)d_in[5];
    const float* ihW1 = (const float*)d_in[6];
    const float* ihb1 = (const float*)d_in[7];
    const float* ihW2 = (const float*)d_in[8];
    const float* ihb2 = (const float*)d_in[9];
    const float* ihWh = (const float*)d_in[10];
    const float* ihbh = (const float*)d_in[11];
    const float* fhW1 = (const float*)d_in[12];
    const float* fhb1 = (const float*)d_in[13];
    const float* fhW2 = (const float*)d_in[14];
    const float* fhb2 = (const float*)d_in[15];
    const float* fhWh = (const float*)d_in[16];
    const float* fhbh = (const float*)d_in[17];
    float* out = (float*)d_out;

    float *S, *G;
    __half *Ph, *Xh, *Qh, *Kh, *Vt, *Yh, *H1h, *H2h;
    __half *WqT, *WkT, *WgT, *W1aT, *W2aT, *W1bT, *W2bT;
    cudaGetSymbolAddress((void**)&S,   g_S);
    cudaGetSymbolAddress((void**)&G,   g_G);
    cudaGetSymbolAddress((void**)&Ph,  g_Ph);
    cudaGetSymbolAddress((void**)&Xh,  g_Xh);
    cudaGetSymbolAddress((void**)&Qh,  g_Qh);
    cudaGetSymbolAddress((void**)&Kh,  g_Kh);
    cudaGetSymbolAddress((void**)&Vt,  g_Vt);
    cudaGetSymbolAddress((void**)&Yh,  g_Yh);
    cudaGetSymbolAddress((void**)&H1h, g_H1h);
    cudaGetSymbolAddress((void**)&H2h, g_H2h);
    cudaGetSymbolAddress((void**)&WqT, g_WqT);
    cudaGetSymbolAddress((void**)&WkT, g_WkT);
    cudaGetSymbolAddress((void**)&WgT, g_WgT);
    cudaGetSymbolAddress((void**)&W1aT, g_W1aT);
    cudaGetSymbolAddress((void**)&W2aT, g_W2aT);
    cudaGetSymbolAddress((void**)&W1bT, g_W1bT);
    cudaGetSymbolAddress((void**)&W2bT, g_W2bT);

    const int N = NN_, D = DD_, H1 = HH1_, H2 = HH2_;
    const float invSqrtD = 1.0f / sqrtf((float)D);

    constexpr int SMEM_H = 4 * 2 * 128 * 12 * 4;   // 49152 B
    cudaFuncSetAttribute(hgemm<0, false, false>, cudaFuncAttributeMaxDynamicSharedMemorySize, SMEM_H);
    cudaFuncSetAttribute(hgemm<0, true , false>, cudaFuncAttributeMaxDynamicSharedMemorySize, SMEM_H);
    cudaFuncSetAttribute(hgemm<0, true , true >, cudaFuncAttributeMaxDynamicSharedMemorySize, SMEM_H);
    cudaFuncSetAttribute(hgemm<1, true , false>, cudaFuncAttributeMaxDynamicSharedMemorySize, SMEM_H);
    cudaFuncSetAttribute(hgemm<2, true , false>, cudaFuncAttributeMaxDynamicSharedMemorySize, SMEM_H);

    // ---- fp16 conversions (X elementwise; weights transposed) ----
    cvt_half_kernel<<<(N * D) / 1024, 256>>>(X, Xh);
    dim3 tb(32, 8);
    cvtT_half_kernel<<<dim3(D / 32, D / 32), tb>>>(Wq, WqT, D, D);
    cvtT_half_kernel<<<dim3(D / 32, D / 32), tb>>>(Wk, WkT, D, D);
    cvtT_half_kernel<<<dim3(D / 32, D / 32), tb>>>(Wg, WgT, D, D);
    cvtT_half_kernel<<<dim3(H1 / 32, D / 32), tb>>>(ihW1, W1aT, D, H1);
    cvtT_half_kernel<<<dim3(H2 / 32, H1 / 32), tb>>>(ihW2, W2aT, H1, H2);
    cvtT_half_kernel<<<dim3(H1 / 32, D / 32), tb>>>(fhW1, W1bT, D, H1);
    cvtT_half_kernel<<<dim3(H2 / 32, H1 / 32), tb>>>(fhW2, W2bT, H1, H2);

    // ---- head 1 on X -> m0,v0,a0,b0 (out[0..4N)) and gate G ----
    hgemm<1, true, false><<<dim3(H1 / 128, N / 128), 256, SMEM_H>>>(Xh,  W1aT, H1h, N, H1, D,  ihb1, nullptr, 1.0f);
    hgemm<1, true, false><<<dim3(H2 / 128, N / 128), 256, SMEM_H>>>(H1h, W2aT, H2h, N, H2, H1, ihb2, nullptr, 1.0f);
    head_final<<<N / 8, 256>>>(H2h, ihWh, ihbh, out, 0, G, gam, N);

    // ---- projections: Qh, Kh row-major; V stored transposed (Vt) ----
    hgemm<0, true, false><<<dim3(D / 128, N / 128), 256, SMEM_H>>>(Xh, WqT, Qh, N, D, D, nullptr, nullptr, 1.0f);
    hgemm<0, true, false><<<dim3(D / 128, N / 128), 256, SMEM_H>>>(Xh, WkT, Kh, N, D, D, nullptr, nullptr, 1.0f);
    hgemm<0, true, true ><<<dim3(D / 128, N / 128), 256, SMEM_H>>>(Xh, WgT, Vt, N, D, D, nullptr, nullptr, 1.0f);

    // ---- S = Q K^T / sqrt(D)  (fp32 out) ----
    hgemm<0, false, false><<<dim3(N / 128, N / 128), 256, SMEM_H>>>(Qh, Kh, S, N, N, D, nullptr, nullptr, invSqrtD);

    // ---- fused softmax stats + gated row normalization -> fp16 P' ----
    softmax_fused<<<N, 256>>>(S, Ph, G, N);

    // ---- Y = X + gelu(P' @ V + bg)  (A=Ph [N,N], B=Vt [D][N] K-major) ----
    hgemm<2, true, false><<<dim3(D / 128, N / 128), 256, SMEM_H>>>(Ph, Vt, Yh, N, D, N, bg, X, 1.0f);

    // ---- head 2 on Y -> mu,v,al,be (out[4N..8N)) ----
    hgemm<1, true, false><<<dim3(H1 / 128, N / 128), 256, SMEM_H>>>(Yh,  W1bT, H1h, N, H1, D,  fhb1, nullptr, 1.0f);
    hgemm<1, true, false><<<dim3(H2 / 128, N / 128), 256, SMEM_H>>>(H1h, W2bT, H2h, N, H2, H1, fhb2, nullptr, 1.0f);
    head_final<<<N / 8, 256>>>(H2h, fhWh, fhbh, out, 4 * N, nullptr, gam, N);
}